// round 1
// baseline (speedup 1.0000x reference)
#include <cuda_runtime.h>

#define BB   32
#define IC   256
#define OC   512
#define HW   56
#define NPIX (HW*HW)
#define NF   64

// scratch (no allocations allowed)
__device__ float g_pooled[BB*IC];
__device__ int   g_sel[BB*NF];

typedef unsigned long long u64;

__device__ __forceinline__ u64 pack2(float a, float b) {
    u64 r; asm("mov.b64 %0, {%1,%2};" : "=l"(r) : "f"(a), "f"(b)); return r;
}
__device__ __forceinline__ void unpack2(u64 v, float &a, float &b) {
    asm("mov.b64 {%0,%1}, %2;" : "=f"(a), "=f"(b) : "l"(v));
}
__device__ __forceinline__ u64 ffma2(u64 a, u64 b, u64 c) {
    u64 d; asm("fma.rn.f32x2 %0, %1, %2, %3;" : "=l"(d) : "l"(a), "l"(b), "l"(c)); return d;
}

// ---------------------------------------------------------------------------
// Kernel 1: global average pool.  one block per (b, ic) plane.
// ---------------------------------------------------------------------------
__global__ void pool_kernel(const float* __restrict__ x) {
    int plane = blockIdx.x;                 // b*IC + ic
    const float* p = x + (size_t)plane * NPIX;
    float s = 0.f;
    for (int i = threadIdx.x; i < NPIX; i += 128) s += p[i];
    #pragma unroll
    for (int o = 16; o; o >>= 1) s += __shfl_down_sync(0xffffffffu, s, o);
    __shared__ float ws[4];
    if ((threadIdx.x & 31) == 0) ws[threadIdx.x >> 5] = s;
    __syncthreads();
    if (threadIdx.x == 0)
        g_pooled[plane] = (ws[0] + ws[1] + ws[2] + ws[3]) * (1.0f / NPIX);
}

// ---------------------------------------------------------------------------
// Kernel 2: router linear + exact top-64 selection (tie-break by index,
// matching jax.lax.top_k).  one block per batch sample, 512 threads.
// ---------------------------------------------------------------------------
__global__ void router_kernel(const float* __restrict__ rw,
                              const float* __restrict__ rb) {
    int b  = blockIdx.x;
    int oc = threadIdx.x;                   // 0..511
    __shared__ float ps[IC];
    __shared__ float rs[OC];
    __shared__ int   cnt;
    if (oc < IC) ps[oc] = g_pooled[b*IC + oc];
    if (oc == 0) cnt = 0;
    __syncthreads();

    float s = rb[oc];
    const float* wrow = rw + (size_t)oc * IC;
    #pragma unroll 8
    for (int i = 0; i < IC; i++) s += ps[i] * wrow[i];
    rs[oc] = s;
    __syncthreads();

    int rank = 0;
    for (int j = 0; j < OC; j++) {
        float v = rs[j];
        rank += (v > s) || (v == s && j < oc);
    }
    if (rank < NF) {
        int pos = atomicAdd(&cnt, 1);
        g_sel[b*NF + pos] = oc;
    }
}

// ---------------------------------------------------------------------------
// Kernel 3: zero the full output (448/512 channels per sample stay zero).
// ---------------------------------------------------------------------------
__global__ void zero_kernel(float4* __restrict__ out, int n4) {
    int i = blockIdx.x * blockDim.x + threadIdx.x;
    int stride = gridDim.x * blockDim.x;
    float4 z = make_float4(0.f, 0.f, 0.f, 0.f);
    for (; i < n4; i += stride) out[i] = z;
}

// ---------------------------------------------------------------------------
// Kernel 4: sparse direct conv, only the 64 selected output channels per b.
// Grid: (oc_chunk 8, row_tile 2, b 32).  Block: (7, 32) = 224 threads.
// Each thread: 8 output cols x 8 output channels, f32x2 packed FMA.
// Per-ic smem: input tile 34x58 (halo + zero pad), weights duplicated pairs.
// ---------------------------------------------------------------------------
#define RT 32
__global__ __launch_bounds__(224, 2)
void conv_kernel(const float* __restrict__ x,
                 const float* __restrict__ w,
                 const float* __restrict__ bias,
                 float* __restrict__ out) {
    __shared__ float  sIn[34*58];
    __shared__ float2 sW[72];               // [oc_local(8)][k(9)] duplicated pairs
    __shared__ int    selc[8];

    const int tx   = threadIdx.x;           // 0..6   (col group of 8)
    const int ty   = threadIdx.y;           // 0..31  (row in tile)
    const int tid  = ty*7 + tx;
    const int ocg  = blockIdx.x;            // 0..7
    const int row0 = blockIdx.y * RT;       // 0 or 32
    const int b    = blockIdx.z;

    if (tid < 8) selc[tid] = g_sel[b*NF + ocg*8 + tid];

    u64 acc[8][4];
    #pragma unroll
    for (int o = 0; o < 8; o++)
        #pragma unroll
        for (int j = 0; j < 4; j++) acc[o][j] = 0ull;

    const float* xb = x + (size_t)b * IC * NPIX;

    for (int ic = 0; ic < IC; ic++) {
        __syncthreads();
        // load input tile rows [row0-1, row0+32], cols [-1, 56], zero-padded
        const float* xp = xb + (size_t)ic * NPIX;
        for (int i = tid; i < 34*58; i += 224) {
            int r  = i / 58;
            int c  = i - r*58;
            int gr = row0 - 1 + r;
            int gc = c - 1;
            float v = 0.f;
            if ((unsigned)gr < HW && (unsigned)gc < HW) v = xp[gr*HW + gc];
            sIn[i] = v;
        }
        // load 8x9 weights for this ic, duplicated into pairs
        if (tid < 72) {
            int o = tid / 9, k = tid - o*9;
            float wv = w[((size_t)selc[o]*IC + ic)*9 + k];
            sW[tid] = make_float2(wv, wv);
        }
        __syncthreads();

        #pragma unroll
        for (int ky = 0; ky < 3; ky++) {
            const float* rowp = sIn + (ty + ky)*58 + 8*tx;
            float v[10];
            #pragma unroll
            for (int j = 0; j < 10; j++) v[j] = rowp[j];
            u64 p[9];
            #pragma unroll
            for (int a = 0; a < 9; a++) p[a] = pack2(v[a], v[a+1]);
            #pragma unroll
            for (int kx = 0; kx < 3; kx++) {
                #pragma unroll
                for (int o = 0; o < 8; o++) {
                    u64 w2 = *reinterpret_cast<const u64*>(&sW[o*9 + ky*3 + kx]);
                    acc[o][0] = ffma2(p[kx+0], w2, acc[o][0]);
                    acc[o][1] = ffma2(p[kx+2], w2, acc[o][1]);
                    acc[o][2] = ffma2(p[kx+4], w2, acc[o][2]);
                    acc[o][3] = ffma2(p[kx+6], w2, acc[o][3]);
                }
            }
        }
    }

    const int orow = row0 + ty;
    if (orow < HW) {
        #pragma unroll
        for (int o = 0; o < 8; o++) {
            int oc = selc[o];
            float bi = bias[oc];
            float r0,r1,r2,r3,r4,r5,r6,r7;
            unpack2(acc[o][0], r0, r1);
            unpack2(acc[o][1], r2, r3);
            unpack2(acc[o][2], r4, r5);
            unpack2(acc[o][3], r6, r7);
            float* op = out + (((size_t)b*OC + oc)*HW + orow)*HW + 8*tx;
            float4 lo = make_float4(r0+bi, r1+bi, r2+bi, r3+bi);
            float4 hi = make_float4(r4+bi, r5+bi, r6+bi, r7+bi);
            *reinterpret_cast<float4*>(op)     = lo;
            *reinterpret_cast<float4*>(op + 4) = hi;
        }
    }
}

// ---------------------------------------------------------------------------
extern "C" void kernel_launch(void* const* d_in, const int* in_sizes, int n_in,
                              void* d_out, int out_size) {
    const float* x    = (const float*)d_in[0];   // [32,256,56,56]
    const float* w    = (const float*)d_in[1];   // [512,256,3,3]
    const float* bias = (const float*)d_in[2];   // [512]
    const float* rw   = (const float*)d_in[3];   // [512,256]
    const float* rb   = (const float*)d_in[4];   // [512]
    float* out = (float*)d_out;                  // [32,512,56,56]

    pool_kernel<<<BB*IC, 128>>>(x);
    router_kernel<<<BB, OC>>>(rw, rb);
    zero_kernel<<<2048, 256>>>((float4*)out, out_size/4);
    conv_kernel<<<dim3(8, 2, BB), dim3(7, 32)>>>(x, w, bias, out);
}

// round 2
// speedup vs baseline: 1.2537x; 1.2537x over previous
#include <cuda_runtime.h>

#define BB   32
#define IC   256
#define OC   512
#define HW   56
#define NPIX (HW*HW)
#define NF   64
#define PITCH 60
#define TROWS 34

// scratch (no allocations allowed)
__device__ float g_pooled[BB*IC];
__device__ int   g_sel[BB*NF];

typedef unsigned long long u64;

__device__ __forceinline__ u64 pack2(float a, float b) {
    u64 r; asm("mov.b64 %0, {%1,%2};" : "=l"(r) : "f"(a), "f"(b)); return r;
}
__device__ __forceinline__ void unpack2(u64 v, float &a, float &b) {
    asm("mov.b64 {%0,%1}, %2;" : "=f"(a), "=f"(b) : "l"(v));
}
__device__ __forceinline__ u64 ffma2(u64 a, u64 b, u64 c) {
    u64 d; asm("fma.rn.f32x2 %0, %1, %2, %3;" : "=l"(d) : "l"(a), "l"(b), "l"(c)); return d;
}

// ---------------------------------------------------------------------------
// Kernel 1: global average pool.  one block per (b, ic) plane, float4 loads.
// ---------------------------------------------------------------------------
__global__ void pool_kernel(const float* __restrict__ x) {
    int plane = blockIdx.x;                 // b*IC + ic
    const float4* p = (const float4*)(x + (size_t)plane * NPIX);
    float s = 0.f;
    for (int i = threadIdx.x; i < NPIX/4; i += 128) {
        float4 v = p[i];
        s += (v.x + v.y) + (v.z + v.w);
    }
    #pragma unroll
    for (int o = 16; o; o >>= 1) s += __shfl_down_sync(0xffffffffu, s, o);
    __shared__ float ws[4];
    if ((threadIdx.x & 31) == 0) ws[threadIdx.x >> 5] = s;
    __syncthreads();
    if (threadIdx.x == 0)
        g_pooled[plane] = (ws[0] + ws[1] + ws[2] + ws[3]) * (1.0f / NPIX);
}

// ---------------------------------------------------------------------------
// Kernel 2: router linear + exact top-64 (tie-break by index, = jax top_k).
// ---------------------------------------------------------------------------
__global__ void router_kernel(const float* __restrict__ rw,
                              const float* __restrict__ rb) {
    int b  = blockIdx.x;
    int oc = threadIdx.x;                   // 0..511
    __shared__ float ps[IC];
    __shared__ float rs[OC];
    __shared__ int   cnt;
    if (oc < IC) ps[oc] = g_pooled[b*IC + oc];
    if (oc == 0) cnt = 0;
    __syncthreads();

    float s = rb[oc];
    const float* wrow = rw + (size_t)oc * IC;
    #pragma unroll 8
    for (int i = 0; i < IC; i++) s += ps[i] * wrow[i];
    rs[oc] = s;
    __syncthreads();

    int rank = 0;
    for (int j = 0; j < OC; j++) {
        float v = rs[j];
        rank += (v > s) || (v == s && j < oc);
    }
    if (rank < NF) {
        int pos = atomicAdd(&cnt, 1);
        g_sel[b*NF + pos] = oc;
    }
}

// ---------------------------------------------------------------------------
// Kernel 3: zero the full output (448/512 channels per sample stay zero).
// ---------------------------------------------------------------------------
__global__ void zero_kernel(float4* __restrict__ out, int n4) {
    int i = blockIdx.x * blockDim.x + threadIdx.x;
    int stride = gridDim.x * blockDim.x;
    float4 z = make_float4(0.f, 0.f, 0.f, 0.f);
    for (; i < n4; i += stride) out[i] = z;
}

// ---------------------------------------------------------------------------
// Kernel 4: sparse direct conv, only the 64 selected output channels per b.
// Grid: (oc_chunk 8, row_tile 2, b 32).  Block: (7, 32) = 224 threads.
// Double-buffered input tile (pitch 60, halo zeroed once) + weights.
// Per thread: 8 oc x 8 cols, f32x2 packed FMA.
// ---------------------------------------------------------------------------
__global__ __launch_bounds__(224, 2)
void conv_kernel(const float* __restrict__ x,
                 const float* __restrict__ w,
                 const float* __restrict__ bias,
                 float* __restrict__ out) {
    __shared__ float  sIn[2][TROWS*PITCH];
    __shared__ float2 sW[2][72];            // [oc_local(8)][k(9)] duplicated pairs
    __shared__ int    selc[8];

    const int tx   = threadIdx.x;           // 0..6   (col group of 8)
    const int ty   = threadIdx.y;           // 0..31  (row in tile)
    const int tid  = ty*7 + tx;
    const int ocg  = blockIdx.x;            // 0..7
    const int row0 = blockIdx.y * 32;       // 0 or 32
    const int b    = blockIdx.z;

    // zero both buffers once: halo cells (cols 0,57..59; out-of-range rows)
    // are never rewritten, so they stay zero for all ic.
    for (int i = tid; i < TROWS*PITCH; i += 224) { sIn[0][i] = 0.f; sIn[1][i] = 0.f; }
    if (tid < 8) selc[tid] = g_sel[b*NF + ocg*8 + tid];
    __syncthreads();

    // weight prefetch pointer (stride per ic = 9 floats)
    const bool wact = tid < 72;
    const float* wp = w;
    if (wact) {
        int o = tid / 9, k = tid - o*9;
        wp = w + ((size_t)selc[o]*IC)*9 + k;
    }

    // interior float4 load slots: 34 rows x 14 float4 = 476 vectors, 3/thread
    int goff[3], soff[3];
    #pragma unroll
    for (int k = 0; k < 3; k++) {
        int idx = tid + k*224;
        int r = idx / 14, j = idx - 14*r;
        int gr = row0 - 1 + r;
        if (idx < 476 && (unsigned)gr < (unsigned)HW) {
            goff[k] = gr*HW + 4*j;          // gmem offset within plane
            soff[k] = r*PITCH + 1 + 4*j;    // smem offset (col shifted +1)
        } else {
            goff[k] = -1; soff[k] = 0;
        }
    }

    const float* xb = x + (size_t)b * IC * NPIX;

    // prologue: load ic=0 into buffer 0
    float4 pre[3];
    #pragma unroll
    for (int k = 0; k < 3; k++)
        if (goff[k] >= 0) pre[k] = *(const float4*)(xb + goff[k]);
    float wpre = wact ? *wp : 0.f;
    #pragma unroll
    for (int k = 0; k < 3; k++)
        if (goff[k] >= 0) {
            float* d = &sIn[0][soff[k]];
            d[0] = pre[k].x; d[1] = pre[k].y; d[2] = pre[k].z; d[3] = pre[k].w;
        }
    if (wact) sW[0][tid] = make_float2(wpre, wpre);
    __syncthreads();

    u64 acc[8][4];
    #pragma unroll
    for (int o = 0; o < 8; o++)
        #pragma unroll
        for (int j = 0; j < 4; j++) acc[o][j] = 0ull;

    for (int ic = 0; ic < IC; ic++) {
        const int cur = ic & 1;
        const bool more = (ic + 1 < IC);

        // prefetch ic+1 into registers (latency overlapped with compute)
        if (more) {
            const float* xn = xb + (size_t)(ic + 1) * NPIX;
            #pragma unroll
            for (int k = 0; k < 3; k++)
                if (goff[k] >= 0) pre[k] = *(const float4*)(xn + goff[k]);
            if (wact) wpre = wp[(ic + 1) * 9];
        }

        // compute from current buffer
        const float*  base = &sIn[cur][ty*PITCH + 8*tx];
        const float2* wsc  = sW[cur];
        #pragma unroll
        for (int ky = 0; ky < 3; ky++) {
            const float* rp = base + ky*PITCH;
            float4 A  = *(const float4*)rp;
            float4 Bv = *(const float4*)(rp + 4);
            float2 Cv = *(const float2*)(rp + 8);
            u64 p0 = pack2(A.x,  A.y ), p1 = pack2(A.y,  A.z );
            u64 p2 = pack2(A.z,  A.w ), p3 = pack2(A.w,  Bv.x);
            u64 p4 = pack2(Bv.x, Bv.y), p5 = pack2(Bv.y, Bv.z);
            u64 p6 = pack2(Bv.z, Bv.w), p7 = pack2(Bv.w, Cv.x);
            u64 p8 = pack2(Cv.x, Cv.y);
            #pragma unroll
            for (int o = 0; o < 8; o++) {
                u64 w0 = *(const u64*)&wsc[o*9 + ky*3 + 0];
                u64 w1 = *(const u64*)&wsc[o*9 + ky*3 + 1];
                u64 w2 = *(const u64*)&wsc[o*9 + ky*3 + 2];
                acc[o][0] = ffma2(p0, w0, acc[o][0]);
                acc[o][1] = ffma2(p2, w0, acc[o][1]);
                acc[o][2] = ffma2(p4, w0, acc[o][2]);
                acc[o][3] = ffma2(p6, w0, acc[o][3]);
                acc[o][0] = ffma2(p1, w1, acc[o][0]);
                acc[o][1] = ffma2(p3, w1, acc[o][1]);
                acc[o][2] = ffma2(p5, w1, acc[o][2]);
                acc[o][3] = ffma2(p7, w1, acc[o][3]);
                acc[o][0] = ffma2(p2, w2, acc[o][0]);
                acc[o][1] = ffma2(p4, w2, acc[o][1]);
                acc[o][2] = ffma2(p6, w2, acc[o][2]);
                acc[o][3] = ffma2(p8, w2, acc[o][3]);
            }
        }

        // store prefetched data into the other buffer, then one barrier
        if (more) {
            const int nxt = cur ^ 1;
            #pragma unroll
            for (int k = 0; k < 3; k++)
                if (goff[k] >= 0) {
                    float* d = &sIn[nxt][soff[k]];
                    d[0] = pre[k].x; d[1] = pre[k].y; d[2] = pre[k].z; d[3] = pre[k].w;
                }
            if (wact) sW[nxt][tid] = make_float2(wpre, wpre);
            __syncthreads();
        }
    }

    const int orow = row0 + ty;
    if (orow < HW) {
        #pragma unroll
        for (int o = 0; o < 8; o++) {
            int oc = selc[o];
            float bi = bias[oc];
            float r0,r1,r2,r3,r4,r5,r6,r7;
            unpack2(acc[o][0], r0, r1);
            unpack2(acc[o][1], r2, r3);
            unpack2(acc[o][2], r4, r5);
            unpack2(acc[o][3], r6, r7);
            float* op = out + (((size_t)b*OC + oc)*HW + orow)*HW + 8*tx;
            float4 lo = make_float4(r0+bi, r1+bi, r2+bi, r3+bi);
            float4 hi = make_float4(r4+bi, r5+bi, r6+bi, r7+bi);
            *reinterpret_cast<float4*>(op)     = lo;
            *reinterpret_cast<float4*>(op + 4) = hi;
        }
    }
}

// ---------------------------------------------------------------------------
extern "C" void kernel_launch(void* const* d_in, const int* in_sizes, int n_in,
                              void* d_out, int out_size) {
    const float* x    = (const float*)d_in[0];   // [32,256,56,56]
    const float* w    = (const float*)d_in[1];   // [512,256,3,3]
    const float* bias = (const float*)d_in[2];   // [512]
    const float* rw   = (const float*)d_in[3];   // [512,256]
    const float* rb   = (const float*)d_in[4];   // [512]
    float* out = (float*)d_out;                  // [32,512,56,56]

    zero_kernel<<<2048, 256>>>((float4*)out, out_size/4);
    pool_kernel<<<BB*IC, 128>>>(x);
    router_kernel<<<BB, OC>>>(rw, rb);
    conv_kernel<<<dim3(8, 2, BB), dim3(7, 32)>>>(x, w, bias, out);
}

// round 4
// speedup vs baseline: 3.3706x; 2.6885x over previous
#include <cuda_runtime.h>
#include <cstdint>

#define BB 32
#define IC 256
#define OC 512
#define HW 56
#define NPIX (HW*HW)
#define NF 64

// scratch (no allocations allowed)
__device__ float g_pooled[BB*IC];
__device__ int   g_sel[BB*NF];

__device__ __forceinline__ float to_tf32(float v){
    float o; asm("cvt.rna.tf32.f32 %0, %1;" : "=f"(o) : "f"(v)); return o;
}

// ---------------------------------------------------------------------------
// Kernel 1: global average pool.
// ---------------------------------------------------------------------------
__global__ void pool_kernel(const float* __restrict__ x) {
    int plane = blockIdx.x;
    const float4* p = (const float4*)(x + (size_t)plane * NPIX);
    float s = 0.f;
    for (int i = threadIdx.x; i < NPIX/4; i += 128) {
        float4 v = p[i];
        s += (v.x + v.y) + (v.z + v.w);
    }
    #pragma unroll
    for (int o = 16; o; o >>= 1) s += __shfl_down_sync(0xffffffffu, s, o);
    __shared__ float ws[4];
    if ((threadIdx.x & 31) == 0) ws[threadIdx.x >> 5] = s;
    __syncthreads();
    if (threadIdx.x == 0)
        g_pooled[plane] = (ws[0] + ws[1] + ws[2] + ws[3]) * (1.0f / NPIX);
}

// ---------------------------------------------------------------------------
// Kernel 2: router linear + exact top-64 (tie-break by index, = jax top_k).
// ---------------------------------------------------------------------------
__global__ void router_kernel(const float* __restrict__ rw,
                              const float* __restrict__ rb) {
    int b  = blockIdx.x;
    int oc = threadIdx.x;
    __shared__ float ps[IC];
    __shared__ float rs[OC];
    __shared__ int   cnt;
    if (oc < IC) ps[oc] = g_pooled[b*IC + oc];
    if (oc == 0) cnt = 0;
    __syncthreads();
    float s = rb[oc];
    const float* wrow = rw + (size_t)oc * IC;
    #pragma unroll 8
    for (int i = 0; i < IC; i++) s += ps[i] * wrow[i];
    rs[oc] = s;
    __syncthreads();
    int rank = 0;
    for (int j = 0; j < OC; j++) {
        float v = rs[j];
        rank += (v > s) || (v == s && j < oc);
    }
    if (rank < NF) {
        int pos = atomicAdd(&cnt, 1);
        g_sel[b*NF + pos] = oc;
    }
}

// ---------------------------------------------------------------------------
// Kernel 3: tf32 mma.sync implicit-GEMM conv on the 64 selected channels,
// with embedded zero-fill of all 512 channels for this CTA's 8-row slab.
// Grid (7 slabs, 32 b), 256 threads (8 warps).  Warp = M64 x N64.
// Window smem: [y 10][x 66][ic-slot 40] (pair-interleaved ic for LDS.64).
// B smem: 2 x [oc 64][slot 40], double buffered per tap.
// ---------------------------------------------------------------------------
#define WIN_FLOATS (10*66*40)
#define BSTG 2560
#define SMEMB ((WIN_FLOATS + 2*BSTG)*4)

__global__ __launch_bounds__(256)
void conv_mma(const float* __restrict__ x, const float* __restrict__ w,
              const float* __restrict__ bias, float* __restrict__ out)
{
    extern __shared__ float sm[];
    float* win = sm;
    float* Bst = sm + WIN_FLOATS;
    __shared__ int   s_sel[64];
    __shared__ float s_bias[64];

    const int tid  = threadIdx.x;
    const int w8   = tid >> 5;            // warp id == output row within slab
    const int lane = tid & 31;
    const int g    = lane >> 2;           // mma groupID
    const int tq   = lane & 3;            // mma threadID-in-group
    const int r0   = blockIdx.x * 8;
    const int b    = blockIdx.y;

    if (tid < 64) {
        int sc = g_sel[b*NF + tid];
        s_sel[tid]  = sc;
        s_bias[tid] = bias[sc];
    }
    // zero window once (halo rows / x-pad stay zero forever)
    for (int i = tid; i < WIN_FLOATS/4; i += 256)
        ((float4*)win)[i] = make_float4(0.f,0.f,0.f,0.f);
    __syncthreads();

    const float* xb   = x + (size_t)b*IC*NPIX;
    float*       outb = out + (size_t)b*OC*NPIX;

    // ---- B fill mapping: thread -> oc = fg+8*w8, k = ftk+4e (e=0..7) ----
    const int ftk = tid & 3;
    const int fg  = (tid >> 2) & 7;
    const int foc = fg + 8*w8;
    const float* wrow = w + (size_t)s_sel[foc]*(IC*9);
    float wp[8];

    #define LDG_B(icg_, tap_) do {                                          \
        const float* p_ = wrow + (size_t)((icg_)*32 + ftk)*9 + (tap_);      \
        _Pragma("unroll")                                                   \
        for (int e = 0; e < 8; e++) wp[e] = p_[36*e];                       \
    } while(0)

    #define STS_B(buf_) do {                                                \
        float* d_ = Bst + (buf_)*BSTG + foc*40 + 2*ftk;                     \
        _Pragma("unroll")                                                   \
        for (int e = 0; e < 8; e++)                                         \
            d_[8*(e>>1) + (e&1)] = to_tf32(wp[e]);                          \
    } while(0)

    // ---- window fill: [y][icq][x][icsub] flat order, 2-way STS max ----
    #define FILL_WIN(icg_) do {                                             \
        for (int i = tid; i < 18560; i += 256) {                            \
            int icsub = i & 3;                                              \
            int t2 = i >> 2;                                                \
            int xx = t2 % 58;                                               \
            int t3 = t2 / 58;                                               \
            int icq = t3 & 7;                                               \
            int y   = t3 >> 3;                                              \
            int icl = icsub + 4*icq;                                        \
            int gy  = r0 - 1 + y;                                           \
            int gx  = xx - 1;                                               \
            float v = 0.f;                                                  \
            if ((unsigned)gy < (unsigned)HW && (unsigned)gx < (unsigned)HW) \
                v = xb[(size_t)((icg_)*32 + icl)*NPIX + gy*HW + gx];        \
            int slot = 8*(icq>>1) + 2*icsub + (icq&1);                      \
            win[(y*66 + xx)*40 + slot] = to_tf32(v);                        \
        }                                                                   \
    } while(0)

    float acc[4][8][4];
    #pragma unroll
    for (int mt = 0; mt < 4; mt++)
        #pragma unroll
        for (int nt = 0; nt < 8; nt++)
            #pragma unroll
            for (int q = 0; q < 4; q++) acc[mt][nt][q] = 0.f;

    // prologue
    FILL_WIN(0);
    LDG_B(0, 0);
    STS_B(0);
    __syncthreads();

    for (int icg = 0; icg < 8; icg++) {
        if (icg) { FILL_WIN(icg); __syncthreads(); }
        for (int tap = 0; tap < 9; tap++) {
            const int chunk = icg*9 + tap;
            const int buf   = chunk & 1;
            const bool more = (chunk < 71);
            if (more) {
                int nc = chunk + 1;
                int ni = nc / 9;
                LDG_B(ni, nc - 9*ni);
            }
            // embedded zero-fill of the output slab (all 512 oc)
            #pragma unroll
            for (int zz = 0; zz < 4; zz++) {
                int v = (chunk*4 + zz)*256 + tid;
                if (v < 57344) {
                    int oc  = v / 112;
                    int rem = v - oc*112;
                    int rr  = rem / 14;
                    int c4  = rem - rr*14;
                    *(float4*)(outb + (size_t)oc*NPIX + (r0+rr)*HW + c4*4)
                        = make_float4(0.f,0.f,0.f,0.f);
                }
            }
            // compute: warp w8 handles output row r0+w8, cols 0..63
            const int dy = tap/3 - 1;
            const int dx = tap - 3*(tap/3) - 1;
            const float* Ab = win + ((w8 + dy + 1)*66 + (dx + 1) + g)*40 + 2*tq;
            const float* Bb = Bst + buf*BSTG + g*40 + 2*tq;
            #pragma unroll
            for (int ks = 0; ks < 4; ks++) {
                uint2 bf[8];
                #pragma unroll
                for (int nt = 0; nt < 8; nt++)
                    bf[nt] = *(const uint2*)(Bb + nt*320 + ks*8);
                #pragma unroll
                for (int mt = 0; mt < 4; mt++) {
                    uint2 aA = *(const uint2*)(Ab + mt*640 + ks*8);
                    uint2 aB = *(const uint2*)(Ab + mt*640 + 320 + ks*8);
                    #pragma unroll
                    for (int nt = 0; nt < 8; nt++) {
                        asm volatile(
                          "mma.sync.aligned.m16n8k8.row.col.f32.tf32.tf32.f32 "
                          "{%0,%1,%2,%3}, {%4,%5,%6,%7}, {%8,%9}, {%0,%1,%2,%3};"
                          : "+f"(acc[mt][nt][0]), "+f"(acc[mt][nt][1]),
                            "+f"(acc[mt][nt][2]), "+f"(acc[mt][nt][3])
                          : "r"(aA.x), "r"(aB.x), "r"(aA.y), "r"(aB.y),
                            "r"(bf[nt].x), "r"(bf[nt].y));
                    }
                }
            }
            if (more) STS_B(buf ^ 1);
            __syncthreads();
        }
    }

    // epilogue: warp w8 -> output row r0+w8
    {
        float* orow = outb + (r0 + w8)*HW;
        #pragma unroll
        for (int nt = 0; nt < 8; nt++) {
            #pragma unroll
            for (int hh = 0; hh < 2; hh++) {
                int n = nt*8 + tq*2 + hh;
                float* op = orow + (size_t)s_sel[n]*NPIX;
                float bi = s_bias[n];
                #pragma unroll
                for (int mt = 0; mt < 4; mt++) {
                    int col = mt*16 + g;
                    op[col] = acc[mt][nt][hh] + bi;          // col <= 55 always
                    if (mt < 3)
                        op[col+8] = acc[mt][nt][2+hh] + bi;  // valid iff < 56
                }
            }
        }
    }
}

// ---------------------------------------------------------------------------
extern "C" void kernel_launch(void* const* d_in, const int* in_sizes, int n_in,
                              void* d_out, int out_size) {
    const float* x    = (const float*)d_in[0];   // [32,256,56,56]
    const float* w    = (const float*)d_in[1];   // [512,256,3,3]
    const float* bias = (const float*)d_in[2];   // [512]
    const float* rw   = (const float*)d_in[3];   // [512,256]
    const float* rb   = (const float*)d_in[4];   // [512]
    float* out = (float*)d_out;                  // [32,512,56,56]

    cudaFuncSetAttribute(conv_mma, cudaFuncAttributeMaxDynamicSharedMemorySize,
                         SMEMB);

    pool_kernel<<<BB*IC, 128>>>(x);
    router_kernel<<<BB, OC>>>(rw, rb);
    conv_mma<<<dim3(7, BB), 256, SMEMB>>>(x, w, bias, out);
}

// round 5
// speedup vs baseline: 4.1147x; 1.2208x over previous
#include <cuda_runtime.h>
#include <cstdint>

#define BB 32
#define IC 256
#define OC 512
#define HW 56
#define NPIX (HW*HW)
#define NF 64

// scratch (no allocations allowed)
__device__ float g_pooled[BB*IC];
__device__ int   g_sel[BB*NF];

__device__ __forceinline__ float to_tf32(float v){
    float o; asm("cvt.rna.tf32.f32 %0, %1;" : "=f"(o) : "f"(v)); return o;
}

// ---------------------------------------------------------------------------
// Kernel 1: global average pool.
// ---------------------------------------------------------------------------
__global__ void pool_kernel(const float* __restrict__ x) {
    int plane = blockIdx.x;
    const float4* p = (const float4*)(x + (size_t)plane * NPIX);
    float s = 0.f;
    for (int i = threadIdx.x; i < NPIX/4; i += 128) {
        float4 v = p[i];
        s += (v.x + v.y) + (v.z + v.w);
    }
    #pragma unroll
    for (int o = 16; o; o >>= 1) s += __shfl_down_sync(0xffffffffu, s, o);
    __shared__ float ws[4];
    if ((threadIdx.x & 31) == 0) ws[threadIdx.x >> 5] = s;
    __syncthreads();
    if (threadIdx.x == 0)
        g_pooled[plane] = (ws[0] + ws[1] + ws[2] + ws[3]) * (1.0f / NPIX);
}

// ---------------------------------------------------------------------------
// Kernel 2: router linear + exact top-64 (tie-break by index, = jax top_k).
// ---------------------------------------------------------------------------
__global__ void router_kernel(const float* __restrict__ rw,
                              const float* __restrict__ rb) {
    int b  = blockIdx.x;
    int oc = threadIdx.x;
    __shared__ float ps[IC];
    __shared__ float rs[OC];
    __shared__ int   cnt;
    if (oc < IC) ps[oc] = g_pooled[b*IC + oc];
    if (oc == 0) cnt = 0;
    __syncthreads();
    float s = rb[oc];
    const float* wrow = rw + (size_t)oc * IC;
    #pragma unroll 8
    for (int i = 0; i < IC; i++) s += ps[i] * wrow[i];
    rs[oc] = s;
    __syncthreads();
    int rank = 0;
    for (int j = 0; j < OC; j++) {
        float v = rs[j];
        rank += (v > s) || (v == s && j < oc);
    }
    if (rank < NF) {
        int pos = atomicAdd(&cnt, 1);
        g_sel[b*NF + pos] = oc;
    }
}

// ---------------------------------------------------------------------------
// Kernel 3: tf32 mma.sync implicit-GEMM conv on the 64 selected channels.
// CTA = (b, 8-row slab, 28-col half-tile).  Grid (7, 2, 32), 256 threads.
// Warp = M32 x N64 (one output row, 28 valid cols).  2 CTAs/SM.
// Window smem: [y 10][x 34 pitch][ic-slot 40] (fill extent x<30).
// B smem: 2 x [oc 64][slot 40] double buffered per tap.
// Embedded zero-fill of all 512 oc for this CTA's 8x28 patch.
// ---------------------------------------------------------------------------
#define XP 34
#define WIN_FLOATS (10*XP*40)
#define BSTG 2560
#define SMEMB ((WIN_FLOATS + 2*BSTG)*4)

__global__ __launch_bounds__(256, 2)
void conv_mma(const float* __restrict__ x, const float* __restrict__ w,
              const float* __restrict__ bias, float* __restrict__ out)
{
    extern __shared__ float sm[];
    float* win = sm;
    float* Bst = sm + WIN_FLOATS;
    __shared__ int   s_sel[64];
    __shared__ float s_bias[64];

    const int tid  = threadIdx.x;
    const int w8   = tid >> 5;            // warp id == output row within slab
    const int lane = tid & 31;
    const int g    = lane >> 2;           // mma groupID
    const int tq   = lane & 3;            // mma threadID-in-group
    const int r0   = blockIdx.x * 8;
    const int xoff = blockIdx.y * 28;
    const int b    = blockIdx.z;

    if (tid < 64) {
        int sc = g_sel[b*NF + tid];
        s_sel[tid]  = sc;
        s_bias[tid] = bias[sc];
    }
    // zero window once (halo/pad cells never rewritten)
    for (int i = tid; i < WIN_FLOATS/4; i += 256)
        ((float4*)win)[i] = make_float4(0.f,0.f,0.f,0.f);
    __syncthreads();

    const float* xb   = x + (size_t)b*IC*NPIX;
    float*       outb = out + (size_t)b*OC*NPIX;

    // ---- B fill mapping: thread -> oc = fg+8*w8, ic' = ftk + 4e ----
    const int ftk = tid & 3;
    const int fg  = (tid >> 2) & 7;
    const int foc = fg + 8*w8;
    const float* wrow = w + (size_t)s_sel[foc]*(IC*9);
    float wp[8];

    #define LDG_B(icg_, tap_) do {                                          \
        const float* p_ = wrow + (size_t)((icg_)*32 + ftk)*9 + (tap_);      \
        _Pragma("unroll")                                                   \
        for (int e = 0; e < 8; e++) wp[e] = p_[36*e];                       \
    } while(0)

    #define STS_B(buf_) do {                                                \
        float* d_ = Bst + (buf_)*BSTG + foc*40 + 2*ftk;                     \
        _Pragma("unroll")                                                   \
        for (int e = 0; e < 8; e++)                                         \
            d_[8*(e>>1) + (e&1)] = to_tf32(wp[e]);                          \
    } while(0)

    // ---- window fill: 10 y x 30 x x 32 ic = 9600 elements per ic-group ----
    #define FILL_WIN(icg_) do {                                             \
        for (int i = tid; i < 9600; i += 256) {                             \
            int icsub = i & 3;                                              \
            int t2 = i >> 2;                                                \
            int xx = t2 % 30;                                               \
            int t3 = t2 / 30;                                               \
            int icq = t3 & 7;                                               \
            int y   = t3 >> 3;                                              \
            int icl = icsub + 4*icq;                                        \
            int gy  = r0 - 1 + y;                                           \
            int gx  = xoff + xx - 1;                                        \
            float v = 0.f;                                                  \
            if ((unsigned)gy < (unsigned)HW && (unsigned)gx < (unsigned)HW) \
                v = xb[(size_t)((icg_)*32 + icl)*NPIX + gy*HW + gx];        \
            int slot = 8*(icq>>1) + 2*icsub + (icq&1);                      \
            win[(y*XP + xx)*40 + slot] = to_tf32(v);                        \
        }                                                                   \
    } while(0)

    float acc[2][8][4];
    #pragma unroll
    for (int mt = 0; mt < 2; mt++)
        #pragma unroll
        for (int nt = 0; nt < 8; nt++)
            #pragma unroll
            for (int q = 0; q < 4; q++) acc[mt][nt][q] = 0.f;

    // prologue
    FILL_WIN(0);
    LDG_B(0, 0);
    STS_B(0);
    __syncthreads();

    for (int icg = 0; icg < 8; icg++) {
        if (icg) { FILL_WIN(icg); __syncthreads(); }
        for (int tap = 0; tap < 9; tap++) {
            const int chunk = icg*9 + tap;
            const int buf   = chunk & 1;
            const bool more = (chunk < 71);
            if (more) {
                int nc = chunk + 1;
                int ni = nc / 9;
                LDG_B(ni, nc - 9*ni);
            }
            // embedded zero-fill of the 8x28 output patch (all 512 oc)
            #pragma unroll
            for (int zz = 0; zz < 2; zz++) {
                int v = (chunk*2 + zz)*256 + tid;
                if (v < 28672) {
                    int oc  = v / 56;
                    int rem = v - oc*56;
                    int rr  = rem / 7;
                    int c4  = rem - rr*7;
                    *(float4*)(outb + (size_t)oc*NPIX + (r0+rr)*HW + xoff + c4*4)
                        = make_float4(0.f,0.f,0.f,0.f);
                }
            }
            // compute: warp w8 -> output row r0+w8, cols xoff..xoff+27
            const int dy = tap/3 - 1;
            const int dx = tap - 3*(tap/3) - 1;
            const float* Ab = win + ((w8 + dy + 1)*XP + (dx + 1) + g)*40 + 2*tq;
            const float* Bb = Bst + buf*BSTG + g*40 + 2*tq;
            #pragma unroll
            for (int ks = 0; ks < 4; ks++) {
                uint2 bf[8];
                #pragma unroll
                for (int nt = 0; nt < 8; nt++)
                    bf[nt] = *(const uint2*)(Bb + nt*320 + ks*8);
                #pragma unroll
                for (int mt = 0; mt < 2; mt++) {
                    uint2 aA = *(const uint2*)(Ab + mt*640 + ks*8);
                    uint2 aB = *(const uint2*)(Ab + mt*640 + 320 + ks*8);
                    #pragma unroll
                    for (int nt = 0; nt < 8; nt++) {
                        asm volatile(
                          "mma.sync.aligned.m16n8k8.row.col.f32.tf32.tf32.f32 "
                          "{%0,%1,%2,%3}, {%4,%5,%6,%7}, {%8,%9}, {%0,%1,%2,%3};"
                          : "+f"(acc[mt][nt][0]), "+f"(acc[mt][nt][1]),
                            "+f"(acc[mt][nt][2]), "+f"(acc[mt][nt][3])
                          : "r"(aA.x), "r"(aB.x), "r"(aA.y), "r"(aB.y),
                            "r"(bf[nt].x), "r"(bf[nt].y));
                    }
                }
            }
            if (more) STS_B(buf ^ 1);
            __syncthreads();
        }
    }

    // epilogue: warp w8 -> output row r0+w8, cols xoff + (mt*16+g), valid < 28
    {
        float* orow = outb + (r0 + w8)*HW + xoff;
        #pragma unroll
        for (int nt = 0; nt < 8; nt++) {
            #pragma unroll
            for (int hh = 0; hh < 2; hh++) {
                int n = nt*8 + tq*2 + hh;
                float* op = orow + (size_t)s_sel[n]*NPIX;
                float bi = s_bias[n];
                #pragma unroll
                for (int mt = 0; mt < 2; mt++) {
                    int col = mt*16 + g;
                    if (col < 28) {
                        op[col]   = acc[mt][nt][hh]   + bi;
                        int col8 = col + 8;
                        if (col8 < 28)
                            op[col8] = acc[mt][nt][2+hh] + bi;
                    }
                }
            }
        }
    }
}

// ---------------------------------------------------------------------------
extern "C" void kernel_launch(void* const* d_in, const int* in_sizes, int n_in,
                              void* d_out, int out_size) {
    const float* x    = (const float*)d_in[0];   // [32,256,56,56]
    const float* w    = (const float*)d_in[1];   // [512,256,3,3]
    const float* bias = (const float*)d_in[2];   // [512]
    const float* rw   = (const float*)d_in[3];   // [512,256]
    const float* rb   = (const float*)d_in[4];   // [512]
    float* out = (float*)d_out;                  // [32,512,56,56]

    cudaFuncSetAttribute(conv_mma, cudaFuncAttributeMaxDynamicSharedMemorySize,
                         SMEMB);

    pool_kernel<<<BB*IC, 128>>>(x);
    router_kernel<<<BB, OC>>>(rw, rb);
    conv_mma<<<dim3(7, 2, BB), 256, SMEMB>>>(x, w, bias, out);
}